// round 13
// baseline (speedup 1.0000x reference)
#include <cuda_runtime.h>
#include <cuda_fp16.h>
#include <cstdint>
#include <math.h>

constexpr int T_TOK = 4096;
constexpr int HID   = 2048;
constexpr int INTER = 5120;
constexpr int NEXP  = 8;
constexpr int ROWS_MAX = 9216;

// ---------- device scratch ----------
__device__ int   g_cnt[NEXP];
__device__ int   g_cursor[NEXP];
__device__ int   g_off[NEXP];
__device__ int   g_region[NEXP];
__device__ int   g_padded_total;
__device__ int   g_tok_e[T_TOK * 2];
__device__ float g_tok_w[T_TOK * 2];
__device__ int   g_tok_rows[T_TOK * 2];
__device__ int   g_row_token[ROWS_MAX];
__device__ __half g_Xg[(size_t)ROWS_MAX * HID];
__device__ __half g_G [(size_t)ROWS_MAX * INTER];
__device__ float  g_Y [(size_t)ROWS_MAX * HID];
__device__ __half g_w2h[(size_t)NEXP * INTER * HID];   // fp16, native [E][K=I][N=H]

// ---------- helpers ----------
__device__ __forceinline__ uint32_t smem_u32(const void* p) {
    uint32_t a;
    asm("{ .reg .u64 t; cvta.to.shared.u64 t, %1; cvt.u32.u64 %0, t; }" : "=r"(a) : "l"(p));
    return a;
}
__device__ __forceinline__ void cp16(uint32_t dst, const void* src) {
    asm volatile("cp.async.cg.shared.global [%0], [%1], 16;" :: "r"(dst), "l"(src));
}
#define CP_COMMIT() asm volatile("cp.async.commit_group;" ::: "memory")
#define CP_WAIT(n)  asm volatile("cp.async.wait_group %0;" :: "n"(n) : "memory")

__device__ __forceinline__ void ldm_x4(uint32_t* r, uint32_t a) {
    asm volatile("ldmatrix.sync.aligned.m8n8.x4.shared.b16 {%0,%1,%2,%3}, [%4];"
        : "=r"(r[0]), "=r"(r[1]), "=r"(r[2]), "=r"(r[3]) : "r"(a));
}
__device__ __forceinline__ void ldm_x4t(uint32_t* r, uint32_t a) {
    asm volatile("ldmatrix.sync.aligned.m8n8.x4.trans.shared.b16 {%0,%1,%2,%3}, [%4];"
        : "=r"(r[0]), "=r"(r[1]), "=r"(r[2]), "=r"(r[3]) : "r"(a));
}
__device__ __forceinline__ void mma16816(float* d, const uint32_t* a, const uint32_t* b) {
    asm volatile("mma.sync.aligned.m16n8k16.row.col.f32.f16.f16.f32 "
        "{%0,%1,%2,%3}, {%4,%5,%6,%7}, {%8,%9}, {%0,%1,%2,%3};"
        : "+f"(d[0]), "+f"(d[1]), "+f"(d[2]), "+f"(d[3])
        : "r"(a[0]), "r"(a[1]), "r"(a[2]), "r"(a[3]), "r"(b[0]), "r"(b[1]));
}
__device__ __forceinline__ float silu(float x) { return x / (1.f + expf(-x)); }

__device__ __forceinline__ uint4 cvt8(float4 v0, float4 v1) {
    __half2 h0 = __floats2half2_rn(v0.x, v0.y);
    __half2 h1 = __floats2half2_rn(v0.z, v0.w);
    __half2 h2 = __floats2half2_rn(v1.x, v1.y);
    __half2 h3 = __floats2half2_rn(v1.z, v1.w);
    uint4 r;
    r.x = *(uint32_t*)&h0; r.y = *(uint32_t*)&h1;
    r.z = *(uint32_t*)&h2; r.w = *(uint32_t*)&h3;
    return r;
}

// ---------- small kernels ----------
__global__ void k_router(const float* __restrict__ hs, const float* __restrict__ gate,
                         float* __restrict__ out) {
    int warp = (blockIdx.x * blockDim.x + threadIdx.x) >> 5;
    int lane = threadIdx.x & 31;
    if (warp >= T_TOK) return;
    const float* x = hs + (size_t)warp * HID;
    float acc[NEXP];
#pragma unroll
    for (int e = 0; e < NEXP; e++) acc[e] = 0.f;
    for (int h = lane; h < HID; h += 32) {
        float xv = x[h];
        const float4* g4 = (const float4*)(gate + (size_t)h * NEXP);
        float4 a = g4[0], b = g4[1];
        acc[0] += xv * a.x; acc[1] += xv * a.y; acc[2] += xv * a.z; acc[3] += xv * a.w;
        acc[4] += xv * b.x; acc[5] += xv * b.y; acc[6] += xv * b.z; acc[7] += xv * b.w;
    }
#pragma unroll
    for (int e = 0; e < NEXP; e++)
#pragma unroll
        for (int o = 16; o; o >>= 1) acc[e] += __shfl_xor_sync(0xffffffffu, acc[e], o);
    if (lane == 0) {
        float* lo = out + (size_t)T_TOK * HID + (size_t)warp * NEXP;
#pragma unroll
        for (int e = 0; e < NEXP; e++) lo[e] = acc[e];
        int e0 = 0; float l0 = acc[0];
#pragma unroll
        for (int e = 1; e < NEXP; e++) if (acc[e] > l0) { l0 = acc[e]; e0 = e; }
        int e1 = -1; float l1 = -1e30f;
#pragma unroll
        for (int e = 0; e < NEXP; e++) if (e != e0 && acc[e] > l1) { l1 = acc[e]; e1 = e; }
        float p1 = expf(l1 - l0);
        float s = 1.f + p1;
        g_tok_e[warp * 2] = e0;      g_tok_e[warp * 2 + 1] = e1;
        g_tok_w[warp * 2] = 1.f / s; g_tok_w[warp * 2 + 1] = p1 / s;
    }
}

__global__ void k_scan() {
    __shared__ int cnt[NEXP];
    int t = threadIdx.x;
    if (t < NEXP) cnt[t] = 0;
    __syncthreads();
    for (int i = t; i < T_TOK * 2; i += blockDim.x)
        atomicAdd(&cnt[g_tok_e[i]], 1);
    __syncthreads();
    if (t == 0) {
        int off = 0;
        for (int e = 0; e < NEXP; e++) {
            g_cnt[e] = cnt[e];
            g_cursor[e] = 0;
            g_off[e] = off;
            int reg = ((cnt[e] + 127) / 128) * 128;
            g_region[e] = reg;
            off += reg;
        }
        g_padded_total = off;
    }
}

__global__ void k_assign() {
    int t = blockIdx.x * blockDim.x + threadIdx.x;
    if (t >= T_TOK) return;
#pragma unroll
    for (int k = 0; k < 2; k++) {
        int e = g_tok_e[t * 2 + k];
        int pos = atomicAdd(&g_cursor[e], 1);
        int row = g_off[e] + pos;
        g_row_token[row] = t;
        g_tok_rows[t * 2 + k] = row;
    }
}

__global__ void k_gather(const float* __restrict__ hs) {
    int r = blockIdx.x;
    int e = 0;
    bool valid = (r < g_padded_total);
    if (valid) {
#pragma unroll
        for (int i = 0; i < NEXP; i++)
            if (r >= g_off[i] && r < g_off[i] + g_region[i]) e = i;
    }
    __half* dst = g_Xg + (size_t)r * HID;
    if (valid && (r - g_off[e]) < g_cnt[e]) {
        int t = g_row_token[r];
        const float4* src = (const float4*)(hs + (size_t)t * HID);
        uint4* d4 = (uint4*)dst;
        for (int i = threadIdx.x; i < HID / 8; i += blockDim.x) {
            float4 v0 = src[2 * i], v1 = src[2 * i + 1];
            d4[i] = cvt8(v0, v1);
        }
    } else {
        uint4* d4 = (uint4*)dst;
        for (int i = threadIdx.x; i < HID / 8; i += blockDim.x)
            d4[i] = make_uint4(0u, 0u, 0u, 0u);
    }
}

__global__ void k_convert(const float* __restrict__ src, __half* __restrict__ dst, int n8) {
    int i = blockIdx.x * blockDim.x + threadIdx.x;
    int stride = gridDim.x * blockDim.x;
    const float4* s4 = (const float4*)src;
    uint4* d4 = (uint4*)dst;
    for (; i < n8; i += stride) {
        float4 v0 = s4[2 * i], v1 = s4[2 * i + 1];
        d4[i] = cvt8(v0, v1);
    }
}

// ---------- GEMM 13: in-kernel f32->f16 weight conversion ----------
constexpr int ST13    = 3;                       // f32 pipeline stages
constexpr int SROW_A  = 40;                      // halves
constexpr int A_STAGE = 128 * SROW_A * 2;        // 10240 B
constexpr int BF_ROW  = 132;                     // floats per staging row
constexpr int BF_STAGE = 32 * BF_ROW * 4;        // 16896 B per matrix per stage
constexpr int SROW_B  = 136;                     // halves per f16 tile row
constexpr int B_H     = 32 * SROW_B * 2;         // 8704 B per f16 tile

constexpr int OFF13_B1F = ST13 * A_STAGE;                    // 30720
constexpr int OFF13_B3F = OFF13_B1F + ST13 * BF_STAGE;       // 81408
constexpr int OFF13_B1H = OFF13_B3F + ST13 * BF_STAGE;       // 132096
constexpr int OFF13_B3H = OFF13_B1H + 2 * B_H;               // 149504
constexpr int SM13      = OFF13_B3H + 2 * B_H;               // 166912

// gemm2 layout (unchanged, 4-stage fp16)
constexpr int STAGES  = 4;
constexpr int B_STAGE = 32 * SROW_B * 2;         // 8704
constexpr int OFF2_B  = STAGES * A_STAGE;        // 40960
constexpr int SM2     = OFF2_B + STAGES * B_STAGE; // 75776

// Fused GEMM1: G = silu(X @ W1) * (X @ W3). K=HID. B loaded as f32, converted in-kernel.
__global__ void __launch_bounds__(256, 1) k_gemm13(const float* __restrict__ w1f,
                                                   const float* __restrict__ w3f) {
    extern __shared__ char sm[];
    int m0 = blockIdx.x * 128;
    if (m0 >= g_padded_total) return;
    int e = 0;
#pragma unroll
    for (int i = 0; i < NEXP; i++)
        if (m0 >= g_off[i] && m0 < g_off[i] + g_region[i]) e = i;
    int n0 = blockIdx.y * 128;

    const __half* Ag = g_Xg + (size_t)m0 * HID;
    const float* B1g = w1f + (size_t)e * HID * INTER + n0;
    const float* B3g = w3f + (size_t)e * HID * INTER + n0;

    int tid = threadIdx.x;
    int wid = tid >> 5, lane = tid & 31;
    int wm = wid >> 2, wn = wid & 3;

    uint32_t uA   = smem_u32(sm);
    uint32_t uB1f = uA + OFF13_B1F;
    uint32_t uB3f = uA + OFF13_B3F;
    uint32_t uB1h = uA + OFF13_B1H;
    uint32_t uB3h = uA + OFF13_B3H;

    int ra0 = tid >> 2,          qa0 = tid & 3;
    int ra1 = (tid + 256) >> 2,  qa1 = tid & 3;
    int vrow = tid >> 5;         // used with i*8 row step? no: vec id pattern below
    (void)vrow;

    float d1[4][4][4], d3[4][4][4];
#pragma unroll
    for (int i = 0; i < 4; i++)
#pragma unroll
        for (int j = 0; j < 4; j++)
#pragma unroll
            for (int k = 0; k < 4; k++) { d1[i][j][k] = 0.f; d3[i][j][k] = 0.f; }

    const int NC = HID / 32;   // 64

    auto load_chunk = [&](int st, int c) {
        int kg = c * 32;
        uint32_t ao = uA + (uint32_t)st * A_STAGE;
        cp16(ao + (uint32_t)(ra0 * SROW_A + qa0 * 8) * 2, Ag + (size_t)ra0 * HID + kg + qa0 * 8);
        cp16(ao + (uint32_t)(ra1 * SROW_A + qa1 * 8) * 2, Ag + (size_t)ra1 * HID + kg + qa1 * 8);
        uint32_t b1o = uB1f + (uint32_t)st * BF_STAGE;
        uint32_t b3o = uB3f + (uint32_t)st * BF_STAGE;
#pragma unroll
        for (int i = 0; i < 4; i++) {                 // 1024 vec16 per matrix
            int v = tid + i * 256;
            int row = v >> 5, c4 = v & 31;
            uint32_t doff = (uint32_t)(row * BF_ROW * 4 + c4 * 16);
            cp16(b1o + doff, B1g + (size_t)(kg + row) * INTER + c4 * 4);
            cp16(b3o + doff, B3g + (size_t)(kg + row) * INTER + c4 * 4);
        }
    };

#pragma unroll
    for (int p = 0; p < ST13 - 1; p++) { load_chunk(p, p); CP_COMMIT(); }

    int bcol = (lane >> 4) * 8;
    for (int c = 0; c < NC; c++) {
        int st = c % ST13;
        CP_WAIT(ST13 - 2);
        __syncthreads();
        if (c + ST13 - 1 < NC) load_chunk((c + ST13 - 1) % ST13, c + ST13 - 1);
        CP_COMMIT();

        // convert f32 staging (stage st) -> f16 tile (buffer c&1)
        {
            int buf = c & 1;
            const char* s1p = sm + OFF13_B1F + st * BF_STAGE;
            const char* s3p = sm + OFF13_B3F + st * BF_STAGE;
            char* d1p = sm + OFF13_B1H + buf * B_H;
            char* d3p = sm + OFF13_B3H + buf * B_H;
#pragma unroll
            for (int i = 0; i < 4; i++) {
                int v = tid + i * 256;
                int row = v >> 5, c4 = v & 31;
                uint32_t so = (uint32_t)(row * BF_ROW * 4 + c4 * 16);
                uint32_t dofs = (uint32_t)(row * SROW_B * 2 + c4 * 8);
                float4 x1 = *(const float4*)(s1p + so);
                __half2 p0 = __floats2half2_rn(x1.x, x1.y);
                __half2 p1 = __floats2half2_rn(x1.z, x1.w);
                uint2 w1v; w1v.x = *(uint32_t*)&p0; w1v.y = *(uint32_t*)&p1;
                *(uint2*)(d1p + dofs) = w1v;
                float4 x3 = *(const float4*)(s3p + so);
                __half2 q0 = __floats2half2_rn(x3.x, x3.y);
                __half2 q1 = __floats2half2_rn(x3.z, x3.w);
                uint2 w3v; w3v.x = *(uint32_t*)&q0; w3v.y = *(uint32_t*)&q1;
                *(uint2*)(d3p + dofs) = w3v;
            }
        }
        __syncthreads();

        uint32_t aB  = uA + (uint32_t)st * A_STAGE;
        uint32_t b1B = uB1h + (uint32_t)(c & 1) * B_H;
        uint32_t b3B = uB3h + (uint32_t)(c & 1) * B_H;
#pragma unroll
        for (int ks = 0; ks < 2; ks++) {
            uint32_t a[4][4];
#pragma unroll
            for (int am = 0; am < 4; am++) {
                int row = wm * 64 + am * 16 + (lane & 15);
                int col = ks * 16 + (lane >> 4) * 8;
                ldm_x4(a[am], aB + (uint32_t)(row * SROW_A + col) * 2);
            }
            int krow = ks * 16 + (lane & 15);
#pragma unroll
            for (int bnp = 0; bnp < 2; bnp++) {
                int ncol = wn * 32 + bnp * 16 + bcol;
                uint32_t off = (uint32_t)(krow * SROW_B + ncol) * 2;
                uint32_t b1[4], b3[4];
                ldm_x4t(b1, b1B + off);
                ldm_x4t(b3, b3B + off);
#pragma unroll
                for (int am = 0; am < 4; am++) {
                    mma16816(d1[am][2 * bnp],     a[am], b1);
                    mma16816(d1[am][2 * bnp + 1], a[am], b1 + 2);
                    mma16816(d3[am][2 * bnp],     a[am], b3);
                    mma16816(d3[am][2 * bnp + 1], a[am], b3 + 2);
                }
            }
        }
    }

    int rbase = m0 + wm * 64 + (lane >> 2);
    int cbase = n0 + wn * 32 + (lane & 3) * 2;
#pragma unroll
    for (int am = 0; am < 4; am++) {
#pragma unroll
        for (int bn = 0; bn < 4; bn++) {
            int r = rbase + am * 16;
            int cc = cbase + bn * 8;
            float* a1 = d1[am][bn];
            float* a3 = d3[am][bn];
            float g0 = silu(a1[0]) * a3[0];
            float g1 = silu(a1[1]) * a3[1];
            float g2 = silu(a1[2]) * a3[2];
            float g3 = silu(a1[3]) * a3[3];
            *(__half2*)(g_G + (size_t)r * INTER + cc)       = __floats2half2_rn(g0, g1);
            *(__half2*)(g_G + (size_t)(r + 8) * INTER + cc) = __floats2half2_rn(g2, g3);
        }
    }
}

// GEMM2: Y = G @ W2, fp32 out. K=INTER. (unchanged; uses pre-converted w2h)
__global__ void __launch_bounds__(256, 1) k_gemm2() {
    extern __shared__ char sm[];
    int m0 = blockIdx.x * 128;
    if (m0 >= g_padded_total) return;
    int e = 0;
#pragma unroll
    for (int i = 0; i < NEXP; i++)
        if (m0 >= g_off[i] && m0 < g_off[i] + g_region[i]) e = i;
    int n0 = blockIdx.y * 128;

    const __half* Ag = g_G + (size_t)m0 * INTER;
    const __half* Bg = g_w2h + (size_t)e * INTER * HID + n0;

    int tid = threadIdx.x;
    int wid = tid >> 5, lane = tid & 31;
    int wm = wid >> 2, wn = wid & 3;

    uint32_t uA = smem_u32(sm);
    uint32_t uB = uA + OFF2_B;

    int ra0 = tid >> 2,          qa0 = tid & 3;
    int ra1 = (tid + 256) >> 2,  qa1 = tid & 3;
    int rb0 = tid >> 4,          qb0 = tid & 15;
    int rb1 = (tid + 256) >> 4,  qb1 = tid & 15;

    float d[4][4][4];
#pragma unroll
    for (int i = 0; i < 4; i++)
#pragma unroll
        for (int j = 0; j < 4; j++)
#pragma unroll
            for (int k = 0; k < 4; k++) d[i][j][k] = 0.f;

    const int NC = INTER / 32;  // 160

    auto load_chunk = [&](int st, int c) {
        int kg = c * 32;
        uint32_t ao = uA + (uint32_t)st * A_STAGE;
        cp16(ao + (uint32_t)(ra0 * SROW_A + qa0 * 8) * 2, Ag + (size_t)ra0 * INTER + kg + qa0 * 8);
        cp16(ao + (uint32_t)(ra1 * SROW_A + qa1 * 8) * 2, Ag + (size_t)ra1 * INTER + kg + qa1 * 8);
        uint32_t bo = uB + (uint32_t)st * B_STAGE;
        cp16(bo + (uint32_t)(rb0 * SROW_B + qb0 * 8) * 2, Bg + (size_t)(kg + rb0) * HID + qb0 * 8);
        cp16(bo + (uint32_t)(rb1 * SROW_B + qb1 * 8) * 2, Bg + (size_t)(kg + rb1) * HID + qb1 * 8);
    };

#pragma unroll
    for (int p = 0; p < STAGES - 1; p++) { load_chunk(p, p); CP_COMMIT(); }

    int bcol = (lane >> 4) * 8;
    for (int c = 0; c < NC; c++) {
        int st = c & (STAGES - 1);
        CP_WAIT(STAGES - 2);
        __syncthreads();
        if (c + STAGES - 1 < NC) load_chunk((c + STAGES - 1) & (STAGES - 1), c + STAGES - 1);
        CP_COMMIT();

        uint32_t aB = uA + (uint32_t)st * A_STAGE;
        uint32_t bB = uB + (uint32_t)st * B_STAGE;
#pragma unroll
        for (int ks = 0; ks < 2; ks++) {
            uint32_t a[4][4];
#pragma unroll
            for (int am = 0; am < 4; am++) {
                int row = wm * 64 + am * 16 + (lane & 15);
                int col = ks * 16 + (lane >> 4) * 8;
                ldm_x4(a[am], aB + (uint32_t)(row * SROW_A + col) * 2);
            }
            int krow = ks * 16 + (lane & 15);
#pragma unroll
            for (int bnp = 0; bnp < 2; bnp++) {
                int ncol = wn * 32 + bnp * 16 + bcol;
                uint32_t b[4];
                ldm_x4t(b, bB + (uint32_t)(krow * SROW_B + ncol) * 2);
#pragma unroll
                for (int am = 0; am < 4; am++) {
                    mma16816(d[am][2 * bnp],     a[am], b);
                    mma16816(d[am][2 * bnp + 1], a[am], b + 2);
                }
            }
        }
    }

    int rbase = m0 + wm * 64 + (lane >> 2);
    int cbase = n0 + wn * 32 + (lane & 3) * 2;
#pragma unroll
    for (int am = 0; am < 4; am++) {
#pragma unroll
        for (int bn = 0; bn < 4; bn++) {
            int r = rbase + am * 16;
            int cc = cbase + bn * 8;
            float* dd = d[am][bn];
            *(float2*)(g_Y + (size_t)r * HID + cc)       = make_float2(dd[0], dd[1]);
            *(float2*)(g_Y + (size_t)(r + 8) * HID + cc) = make_float2(dd[2], dd[3]);
        }
    }
}

__global__ void k_combine(float* __restrict__ out) {
    int t = blockIdx.x;
    int r0 = g_tok_rows[t * 2], r1 = g_tok_rows[t * 2 + 1];
    float w0 = g_tok_w[t * 2], w1 = g_tok_w[t * 2 + 1];
    const float4* y0 = (const float4*)(g_Y + (size_t)r0 * HID);
    const float4* y1 = (const float4*)(g_Y + (size_t)r1 * HID);
    float4* o = (float4*)(out + (size_t)t * HID);
    for (int i = threadIdx.x; i < HID / 4; i += blockDim.x) {
        float4 a = y0[i], b = y1[i];
        float4 v;
        v.x = w0 * a.x + w1 * b.x;
        v.y = w0 * a.y + w1 * b.y;
        v.z = w0 * a.z + w1 * b.z;
        v.w = w0 * a.w + w1 * b.w;
        o[i] = v;
    }
}

// ---------- launch ----------
extern "C" void kernel_launch(void* const* d_in, const int* in_sizes, int n_in,
                              void* d_out, int out_size) {
    const float* hs   = (const float*)d_in[0];
    const float* gate = (const float*)d_in[1];
    const float* w1   = (const float*)d_in[2];
    const float* w3   = (const float*)d_in[3];
    const float* w2   = (const float*)d_in[4];
    float* out = (float*)d_out;

    __half* w2h;
    cudaGetSymbolAddress((void**)&w2h, g_w2h);

    static cudaStream_t s1 = nullptr, s2 = nullptr;
    static cudaEvent_t evF = nullptr, evR = nullptr, evW2 = nullptr;
    if (!s1) {
        cudaStreamCreateWithFlags(&s1, cudaStreamNonBlocking);
        cudaStreamCreateWithFlags(&s2, cudaStreamNonBlocking);
        cudaEventCreateWithFlags(&evF,  cudaEventDisableTiming);
        cudaEventCreateWithFlags(&evR,  cudaEventDisableTiming);
        cudaEventCreateWithFlags(&evW2, cudaEventDisableTiming);
        cudaFuncSetAttribute(k_gemm13, cudaFuncAttributeMaxDynamicSharedMemorySize, SM13);
        cudaFuncSetAttribute(k_gemm2,  cudaFuncAttributeMaxDynamicSharedMemorySize, SM2);
    }

    const int WN8 = NEXP * HID * INTER / 8;

    cudaEventRecord(evF, 0);
    cudaStreamWaitEvent(s1, evF, 0);
    cudaStreamWaitEvent(s2, evF, 0);

    // s1: routing chain
    k_router<<<T_TOK / 8, 256, 0, s1>>>(hs, gate, out);
    k_scan<<<1, 256, 0, s1>>>();
    k_assign<<<T_TOK / 256, 256, 0, s1>>>();
    k_gather<<<ROWS_MAX, 128, 0, s1>>>(hs);
    cudaEventRecord(evR, s1);

    // s2: w2 convert, fully hidden under gemm13
    k_convert<<<4096, 256, 0, s2>>>(w2, w2h, WN8);
    cudaEventRecord(evW2, s2);

    // main: gemm13 starts right after routing (no weight convert on critical path)
    cudaStreamWaitEvent(0, evR, 0);
    k_gemm13<<<dim3(ROWS_MAX / 128, INTER / 128), 256, SM13>>>(w1, w3);

    cudaStreamWaitEvent(0, evW2, 0);
    k_gemm2 <<<dim3(ROWS_MAX / 128, HID / 128), 256, SM2>>>();

    k_combine<<<T_TOK, 256>>>(out);
}

// round 14
// speedup vs baseline: 1.2855x; 1.2855x over previous
#include <cuda_runtime.h>
#include <cuda_fp16.h>
#include <cstdint>
#include <math.h>

constexpr int T_TOK = 4096;
constexpr int HID   = 2048;
constexpr int INTER = 5120;
constexpr int NEXP  = 8;
constexpr int ROWS_MAX = 9216;

// ---------- device scratch ----------
__device__ int   g_cnt[NEXP];
__device__ int   g_cursor[NEXP];
__device__ int   g_off[NEXP];
__device__ int   g_region[NEXP];
__device__ int   g_padded_total;
__device__ int   g_tok_e[T_TOK * 2];
__device__ float g_tok_w[T_TOK * 2];
__device__ int   g_tok_rows[T_TOK * 2];
__device__ int   g_row_token[ROWS_MAX];
__device__ __half g_Xg[(size_t)ROWS_MAX * HID];
__device__ __half g_G [(size_t)ROWS_MAX * INTER];
__device__ float  g_Y [(size_t)ROWS_MAX * HID];
__device__ __half g_w1h[(size_t)NEXP * HID * INTER];   // fp16, native [E][K=H][N=I]
__device__ __half g_w3h[(size_t)NEXP * HID * INTER];
__device__ __half g_w2h[(size_t)NEXP * INTER * HID];   // fp16, native [E][K=I][N=H]

// ---------- helpers ----------
__device__ __forceinline__ uint32_t smem_u32(const void* p) {
    uint32_t a;
    asm("{ .reg .u64 t; cvta.to.shared.u64 t, %1; cvt.u32.u64 %0, t; }" : "=r"(a) : "l"(p));
    return a;
}
__device__ __forceinline__ void cp16(uint32_t dst, const void* src) {
    asm volatile("cp.async.cg.shared.global [%0], [%1], 16;" :: "r"(dst), "l"(src));
}
#define CP_COMMIT() asm volatile("cp.async.commit_group;" ::: "memory")
#define CP_WAIT(n)  asm volatile("cp.async.wait_group %0;" :: "n"(n) : "memory")

__device__ __forceinline__ void ldm_x4(uint32_t* r, uint32_t a) {
    asm volatile("ldmatrix.sync.aligned.m8n8.x4.shared.b16 {%0,%1,%2,%3}, [%4];"
        : "=r"(r[0]), "=r"(r[1]), "=r"(r[2]), "=r"(r[3]) : "r"(a));
}
__device__ __forceinline__ void ldm_x4t(uint32_t* r, uint32_t a) {
    asm volatile("ldmatrix.sync.aligned.m8n8.x4.trans.shared.b16 {%0,%1,%2,%3}, [%4];"
        : "=r"(r[0]), "=r"(r[1]), "=r"(r[2]), "=r"(r[3]) : "r"(a));
}
__device__ __forceinline__ void mma16816(float* d, const uint32_t* a, const uint32_t* b) {
    asm volatile("mma.sync.aligned.m16n8k16.row.col.f32.f16.f16.f32 "
        "{%0,%1,%2,%3}, {%4,%5,%6,%7}, {%8,%9}, {%0,%1,%2,%3};"
        : "+f"(d[0]), "+f"(d[1]), "+f"(d[2]), "+f"(d[3])
        : "r"(a[0]), "r"(a[1]), "r"(a[2]), "r"(a[3]), "r"(b[0]), "r"(b[1]));
}
__device__ __forceinline__ float silu(float x) { return x / (1.f + expf(-x)); }

__device__ __forceinline__ uint4 cvt8(float4 v0, float4 v1) {
    __half2 h0 = __floats2half2_rn(v0.x, v0.y);
    __half2 h1 = __floats2half2_rn(v0.z, v0.w);
    __half2 h2 = __floats2half2_rn(v1.x, v1.y);
    __half2 h3 = __floats2half2_rn(v1.z, v1.w);
    uint4 r;
    r.x = *(uint32_t*)&h0; r.y = *(uint32_t*)&h1;
    r.z = *(uint32_t*)&h2; r.w = *(uint32_t*)&h3;
    return r;
}

// ---------- small kernels ----------
__global__ void k_router(const float* __restrict__ hs, const float* __restrict__ gate,
                         float* __restrict__ out) {
    int warp = (blockIdx.x * blockDim.x + threadIdx.x) >> 5;
    int lane = threadIdx.x & 31;
    if (warp >= T_TOK) return;
    const float* x = hs + (size_t)warp * HID;
    float acc[NEXP];
#pragma unroll
    for (int e = 0; e < NEXP; e++) acc[e] = 0.f;
    for (int h = lane; h < HID; h += 32) {
        float xv = x[h];
        const float4* g4 = (const float4*)(gate + (size_t)h * NEXP);
        float4 a = g4[0], b = g4[1];
        acc[0] += xv * a.x; acc[1] += xv * a.y; acc[2] += xv * a.z; acc[3] += xv * a.w;
        acc[4] += xv * b.x; acc[5] += xv * b.y; acc[6] += xv * b.z; acc[7] += xv * b.w;
    }
#pragma unroll
    for (int e = 0; e < NEXP; e++)
#pragma unroll
        for (int o = 16; o; o >>= 1) acc[e] += __shfl_xor_sync(0xffffffffu, acc[e], o);
    if (lane == 0) {
        float* lo = out + (size_t)T_TOK * HID + (size_t)warp * NEXP;
#pragma unroll
        for (int e = 0; e < NEXP; e++) lo[e] = acc[e];
        int e0 = 0; float l0 = acc[0];
#pragma unroll
        for (int e = 1; e < NEXP; e++) if (acc[e] > l0) { l0 = acc[e]; e0 = e; }
        int e1 = -1; float l1 = -1e30f;
#pragma unroll
        for (int e = 0; e < NEXP; e++) if (e != e0 && acc[e] > l1) { l1 = acc[e]; e1 = e; }
        float p1 = expf(l1 - l0);
        float s = 1.f + p1;
        g_tok_e[warp * 2] = e0;      g_tok_e[warp * 2 + 1] = e1;
        g_tok_w[warp * 2] = 1.f / s; g_tok_w[warp * 2 + 1] = p1 / s;
    }
}

__global__ void k_scan() {
    __shared__ int cnt[NEXP];
    int t = threadIdx.x;
    if (t < NEXP) cnt[t] = 0;
    __syncthreads();
    for (int i = t; i < T_TOK * 2; i += blockDim.x)
        atomicAdd(&cnt[g_tok_e[i]], 1);
    __syncthreads();
    if (t == 0) {
        int off = 0;
        for (int e = 0; e < NEXP; e++) {
            g_cnt[e] = cnt[e];
            g_cursor[e] = 0;
            g_off[e] = off;
            int reg = ((cnt[e] + 127) / 128) * 128;
            g_region[e] = reg;
            off += reg;
        }
        g_padded_total = off;
    }
}

__global__ void k_assign() {
    int t = blockIdx.x * blockDim.x + threadIdx.x;
    if (t >= T_TOK) return;
#pragma unroll
    for (int k = 0; k < 2; k++) {
        int e = g_tok_e[t * 2 + k];
        int pos = atomicAdd(&g_cursor[e], 1);
        int row = g_off[e] + pos;
        g_row_token[row] = t;
        g_tok_rows[t * 2 + k] = row;
    }
}

__global__ void k_gather(const float* __restrict__ hs) {
    int r = blockIdx.x;
    int e = 0;
    bool valid = (r < g_padded_total);
    if (valid) {
#pragma unroll
        for (int i = 0; i < NEXP; i++)
            if (r >= g_off[i] && r < g_off[i] + g_region[i]) e = i;
    }
    __half* dst = g_Xg + (size_t)r * HID;
    if (valid && (r - g_off[e]) < g_cnt[e]) {
        int t = g_row_token[r];
        const float4* src = (const float4*)(hs + (size_t)t * HID);
        uint4* d4 = (uint4*)dst;
        for (int i = threadIdx.x; i < HID / 8; i += blockDim.x) {
            float4 v0 = src[2 * i], v1 = src[2 * i + 1];
            d4[i] = cvt8(v0, v1);
        }
    } else {
        uint4* d4 = (uint4*)dst;
        for (int i = threadIdx.x; i < HID / 8; i += blockDim.x)
            d4[i] = make_uint4(0u, 0u, 0u, 0u);
    }
}

// convert TWO fp32 arrays -> fp16 in one launch; 32B in -> 16B coalesced out
__global__ void k_convert2(const float* __restrict__ s1, __half* __restrict__ d1,
                           const float* __restrict__ s2, __half* __restrict__ d2c,
                           int n8) {
    int i = blockIdx.x * blockDim.x + threadIdx.x;
    int stride = gridDim.x * blockDim.x;
    for (; i < 2 * n8; i += stride) {
        const float4* s4 = (i < n8) ? (const float4*)s1 : (const float4*)s2;
        uint4* dd        = (i < n8) ? (uint4*)d1 : (uint4*)d2c;
        int j = (i < n8) ? i : i - n8;
        float4 v0 = s4[2 * j], v1 = s4[2 * j + 1];
        dd[j] = cvt8(v0, v1);
    }
}

__global__ void k_convert(const float* __restrict__ src, __half* __restrict__ dst, int n8) {
    int i = blockIdx.x * blockDim.x + threadIdx.x;
    int stride = gridDim.x * blockDim.x;
    const float4* s4 = (const float4*)src;
    uint4* d4 = (uint4*)dst;
    for (; i < n8; i += stride) {
        float4 v0 = s4[2 * i], v1 = s4[2 * i + 1];
        d4[i] = cvt8(v0, v1);
    }
}

// ---------- GEMM kernels ----------
constexpr int STAGES  = 4;
constexpr int SROW_A  = 40;
constexpr int A_STAGE = 128 * SROW_A * 2;     // 10240 B
constexpr int SROW_B  = 136;
constexpr int B_STAGE = 32 * SROW_B * 2;      // 8704 B
constexpr int OFF_B1  = STAGES * A_STAGE;                 // 40960
constexpr int OFF_B3  = OFF_B1 + STAGES * B_STAGE;        // 75776
constexpr int SM13    = OFF_B3 + STAGES * B_STAGE;        // 110592
constexpr int SM2     = OFF_B1 + STAGES * B_STAGE;        // 75776

// Fused GEMM1: G = silu(X @ W1) * (X @ W3). K=HID. fp32 accum.
__global__ void __launch_bounds__(256, 1) k_gemm13() {
    extern __shared__ char sm[];
    int m0 = blockIdx.x * 128;
    if (m0 >= g_padded_total) return;
    int e = 0;
#pragma unroll
    for (int i = 0; i < NEXP; i++)
        if (m0 >= g_off[i] && m0 < g_off[i] + g_region[i]) e = i;
    int n0 = blockIdx.y * 128;

    const __half* Ag  = g_Xg + (size_t)m0 * HID;
    const __half* B1g = g_w1h + (size_t)e * HID * INTER + n0;
    const __half* B3g = g_w3h + (size_t)e * HID * INTER + n0;

    int tid = threadIdx.x;
    int wid = tid >> 5, lane = tid & 31;
    int wm = wid >> 2, wn = wid & 3;

    uint32_t uA  = smem_u32(sm);
    uint32_t uB1 = uA + OFF_B1;
    uint32_t uB3 = uA + OFF_B3;

    int ra0 = tid >> 2,          qa0 = tid & 3;
    int ra1 = (tid + 256) >> 2,  qa1 = tid & 3;
    int rb0 = tid >> 4,          qb0 = tid & 15;
    int rb1 = (tid + 256) >> 4,  qb1 = tid & 15;

    float d1[4][4][4], d3[4][4][4];
#pragma unroll
    for (int i = 0; i < 4; i++)
#pragma unroll
        for (int j = 0; j < 4; j++)
#pragma unroll
            for (int k = 0; k < 4; k++) { d1[i][j][k] = 0.f; d3[i][j][k] = 0.f; }

    const int NC = HID / 32;   // 64

    auto load_chunk = [&](int st, int c) {
        int kg = c * 32;
        uint32_t ao = uA + (uint32_t)st * A_STAGE;
        cp16(ao + (uint32_t)(ra0 * SROW_A + qa0 * 8) * 2, Ag + (size_t)ra0 * HID + kg + qa0 * 8);
        cp16(ao + (uint32_t)(ra1 * SROW_A + qa1 * 8) * 2, Ag + (size_t)ra1 * HID + kg + qa1 * 8);
        uint32_t b1o = uB1 + (uint32_t)st * B_STAGE;
        uint32_t b3o = uB3 + (uint32_t)st * B_STAGE;
        cp16(b1o + (uint32_t)(rb0 * SROW_B + qb0 * 8) * 2, B1g + (size_t)(kg + rb0) * INTER + qb0 * 8);
        cp16(b1o + (uint32_t)(rb1 * SROW_B + qb1 * 8) * 2, B1g + (size_t)(kg + rb1) * INTER + qb1 * 8);
        cp16(b3o + (uint32_t)(rb0 * SROW_B + qb0 * 8) * 2, B3g + (size_t)(kg + rb0) * INTER + qb0 * 8);
        cp16(b3o + (uint32_t)(rb1 * SROW_B + qb1 * 8) * 2, B3g + (size_t)(kg + rb1) * INTER + qb1 * 8);
    };

#pragma unroll
    for (int p = 0; p < STAGES - 1; p++) { load_chunk(p, p); CP_COMMIT(); }

    int bcol = (lane >> 4) * 8;
    for (int c = 0; c < NC; c++) {
        int st = c & (STAGES - 1);
        CP_WAIT(STAGES - 2);
        __syncthreads();
        if (c + STAGES - 1 < NC) load_chunk((c + STAGES - 1) & (STAGES - 1), c + STAGES - 1);
        CP_COMMIT();

        uint32_t aB  = uA  + (uint32_t)st * A_STAGE;
        uint32_t b1B = uB1 + (uint32_t)st * B_STAGE;
        uint32_t b3B = uB3 + (uint32_t)st * B_STAGE;
#pragma unroll
        for (int ks = 0; ks < 2; ks++) {
            uint32_t a[4][4];
#pragma unroll
            for (int am = 0; am < 4; am++) {
                int row = wm * 64 + am * 16 + (lane & 15);
                int col = ks * 16 + (lane >> 4) * 8;
                ldm_x4(a[am], aB + (uint32_t)(row * SROW_A + col) * 2);
            }
            int krow = ks * 16 + (lane & 15);
#pragma unroll
            for (int bnp = 0; bnp < 2; bnp++) {
                int ncol = wn * 32 + bnp * 16 + bcol;
                uint32_t off = (uint32_t)(krow * SROW_B + ncol) * 2;
                uint32_t b1[4], b3[4];
                ldm_x4t(b1, b1B + off);
                ldm_x4t(b3, b3B + off);
#pragma unroll
                for (int am = 0; am < 4; am++) {
                    mma16816(d1[am][2 * bnp],     a[am], b1);
                    mma16816(d1[am][2 * bnp + 1], a[am], b1 + 2);
                    mma16816(d3[am][2 * bnp],     a[am], b3);
                    mma16816(d3[am][2 * bnp + 1], a[am], b3 + 2);
                }
            }
        }
    }

    int rbase = m0 + wm * 64 + (lane >> 2);
    int cbase = n0 + wn * 32 + (lane & 3) * 2;
#pragma unroll
    for (int am = 0; am < 4; am++) {
#pragma unroll
        for (int bn = 0; bn < 4; bn++) {
            int r = rbase + am * 16;
            int cc = cbase + bn * 8;
            float* a1 = d1[am][bn];
            float* a3 = d3[am][bn];
            float g0 = silu(a1[0]) * a3[0];
            float g1 = silu(a1[1]) * a3[1];
            float g2 = silu(a1[2]) * a3[2];
            float g3 = silu(a1[3]) * a3[3];
            *(__half2*)(g_G + (size_t)r * INTER + cc)       = __floats2half2_rn(g0, g1);
            *(__half2*)(g_G + (size_t)(r + 8) * INTER + cc) = __floats2half2_rn(g2, g3);
        }
    }
}

// GEMM2: Y = G @ W2, fp32 out. K=INTER. occupancy 2 for barrier-latency hiding.
__global__ void __launch_bounds__(256, 2) k_gemm2() {
    extern __shared__ char sm[];
    int m0 = blockIdx.x * 128;
    if (m0 >= g_padded_total) return;
    int e = 0;
#pragma unroll
    for (int i = 0; i < NEXP; i++)
        if (m0 >= g_off[i] && m0 < g_off[i] + g_region[i]) e = i;
    int n0 = blockIdx.y * 128;

    const __half* Ag = g_G + (size_t)m0 * INTER;
    const __half* Bg = g_w2h + (size_t)e * INTER * HID + n0;

    int tid = threadIdx.x;
    int wid = tid >> 5, lane = tid & 31;
    int wm = wid >> 2, wn = wid & 3;

    uint32_t uA = smem_u32(sm);
    uint32_t uB = uA + OFF_B1;

    int ra0 = tid >> 2,          qa0 = tid & 3;
    int ra1 = (tid + 256) >> 2,  qa1 = tid & 3;
    int rb0 = tid >> 4,          qb0 = tid & 15;
    int rb1 = (tid + 256) >> 4,  qb1 = tid & 15;

    float d[4][4][4];
#pragma unroll
    for (int i = 0; i < 4; i++)
#pragma unroll
        for (int j = 0; j < 4; j++)
#pragma unroll
            for (int k = 0; k < 4; k++) d[i][j][k] = 0.f;

    const int NC = INTER / 32;  // 160

    auto load_chunk = [&](int st, int c) {
        int kg = c * 32;
        uint32_t ao = uA + (uint32_t)st * A_STAGE;
        cp16(ao + (uint32_t)(ra0 * SROW_A + qa0 * 8) * 2, Ag + (size_t)ra0 * INTER + kg + qa0 * 8);
        cp16(ao + (uint32_t)(ra1 * SROW_A + qa1 * 8) * 2, Ag + (size_t)ra1 * INTER + kg + qa1 * 8);
        uint32_t bo = uB + (uint32_t)st * B_STAGE;
        cp16(bo + (uint32_t)(rb0 * SROW_B + qb0 * 8) * 2, Bg + (size_t)(kg + rb0) * HID + qb0 * 8);
        cp16(bo + (uint32_t)(rb1 * SROW_B + qb1 * 8) * 2, Bg + (size_t)(kg + rb1) * HID + qb1 * 8);
    };

#pragma unroll
    for (int p = 0; p < STAGES - 1; p++) { load_chunk(p, p); CP_COMMIT(); }

    int bcol = (lane >> 4) * 8;
    for (int c = 0; c < NC; c++) {
        int st = c & (STAGES - 1);
        CP_WAIT(STAGES - 2);
        __syncthreads();
        if (c + STAGES - 1 < NC) load_chunk((c + STAGES - 1) & (STAGES - 1), c + STAGES - 1);
        CP_COMMIT();

        uint32_t aB = uA + (uint32_t)st * A_STAGE;
        uint32_t bB = uB + (uint32_t)st * B_STAGE;
#pragma unroll
        for (int ks = 0; ks < 2; ks++) {
            uint32_t a[4][4];
#pragma unroll
            for (int am = 0; am < 4; am++) {
                int row = wm * 64 + am * 16 + (lane & 15);
                int col = ks * 16 + (lane >> 4) * 8;
                ldm_x4(a[am], aB + (uint32_t)(row * SROW_A + col) * 2);
            }
            int krow = ks * 16 + (lane & 15);
#pragma unroll
            for (int bnp = 0; bnp < 2; bnp++) {
                int ncol = wn * 32 + bnp * 16 + bcol;
                uint32_t b[4];
                ldm_x4t(b, bB + (uint32_t)(krow * SROW_B + ncol) * 2);
#pragma unroll
                for (int am = 0; am < 4; am++) {
                    mma16816(d[am][2 * bnp],     a[am], b);
                    mma16816(d[am][2 * bnp + 1], a[am], b + 2);
                }
            }
        }
    }

    int rbase = m0 + wm * 64 + (lane >> 2);
    int cbase = n0 + wn * 32 + (lane & 3) * 2;
#pragma unroll
    for (int am = 0; am < 4; am++) {
#pragma unroll
        for (int bn = 0; bn < 4; bn++) {
            int r = rbase + am * 16;
            int cc = cbase + bn * 8;
            float* dd = d[am][bn];
            *(float2*)(g_Y + (size_t)r * HID + cc)       = make_float2(dd[0], dd[1]);
            *(float2*)(g_Y + (size_t)(r + 8) * HID + cc) = make_float2(dd[2], dd[3]);
        }
    }
}

__global__ void k_combine(float* __restrict__ out) {
    int t = blockIdx.x;
    int r0 = g_tok_rows[t * 2], r1 = g_tok_rows[t * 2 + 1];
    float w0 = g_tok_w[t * 2], w1 = g_tok_w[t * 2 + 1];
    const float4* y0 = (const float4*)(g_Y + (size_t)r0 * HID);
    const float4* y1 = (const float4*)(g_Y + (size_t)r1 * HID);
    float4* o = (float4*)(out + (size_t)t * HID);
    for (int i = threadIdx.x; i < HID / 4; i += blockDim.x) {
        float4 a = y0[i], b = y1[i];
        float4 v;
        v.x = w0 * a.x + w1 * b.x;
        v.y = w0 * a.y + w1 * b.y;
        v.z = w0 * a.z + w1 * b.z;
        v.w = w0 * a.w + w1 * b.w;
        o[i] = v;
    }
}

// ---------- launch ----------
extern "C" void kernel_launch(void* const* d_in, const int* in_sizes, int n_in,
                              void* d_out, int out_size) {
    const float* hs   = (const float*)d_in[0];
    const float* gate = (const float*)d_in[1];
    const float* w1   = (const float*)d_in[2];
    const float* w3   = (const float*)d_in[3];
    const float* w2   = (const float*)d_in[4];
    float* out = (float*)d_out;

    __half *w1h, *w3h, *w2h;
    cudaGetSymbolAddress((void**)&w1h, g_w1h);
    cudaGetSymbolAddress((void**)&w3h, g_w3h);
    cudaGetSymbolAddress((void**)&w2h, g_w2h);

    static cudaStream_t s1 = nullptr, s2 = nullptr;
    static cudaEvent_t evF = nullptr, evR = nullptr, evC2 = nullptr, evW2 = nullptr;
    if (!s1) {
        cudaStreamCreateWithFlags(&s1, cudaStreamNonBlocking);
        cudaStreamCreateWithFlags(&s2, cudaStreamNonBlocking);
        cudaEventCreateWithFlags(&evF,  cudaEventDisableTiming);
        cudaEventCreateWithFlags(&evR,  cudaEventDisableTiming);
        cudaEventCreateWithFlags(&evC2, cudaEventDisableTiming);
        cudaEventCreateWithFlags(&evW2, cudaEventDisableTiming);
        cudaFuncSetAttribute(k_gemm13, cudaFuncAttributeMaxDynamicSharedMemorySize, SM13);
        cudaFuncSetAttribute(k_gemm2,  cudaFuncAttributeMaxDynamicSharedMemorySize, SM2);
    }

    const int WN8 = NEXP * HID * INTER / 8;

    cudaEventRecord(evF, 0);
    cudaStreamWaitEvent(s1, evF, 0);
    cudaStreamWaitEvent(s2, evF, 0);

    // s1: routing chain (parallel with convert2)
    k_router<<<T_TOK / 8, 256, 0, s1>>>(hs, gate, out);
    k_scan<<<1, 256, 0, s1>>>();
    k_assign<<<T_TOK / 256, 256, 0, s1>>>();
    k_gather<<<ROWS_MAX, 128, 0, s1>>>(hs);
    cudaEventRecord(evR, s1);

    // main: critical-path w1+w3 convert gets the FULL DRAM bandwidth
    k_convert2<<<8192, 256>>>(w1, w1h, w3, w3h, WN8);
    cudaEventRecord(evC2, 0);
    cudaStreamWaitEvent(0, evR, 0);

    k_gemm13<<<dim3(ROWS_MAX / 128, INTER / 128), 256, SM13>>>();

    // s2: w2 convert AFTER convert2 (no front-phase contention), hidden under gemm13
    cudaStreamWaitEvent(s2, evC2, 0);
    k_convert<<<4096, 256, 0, s2>>>(w2, w2h, WN8);
    cudaEventRecord(evW2, s2);

    cudaStreamWaitEvent(0, evW2, 0);
    k_gemm2 <<<dim3(ROWS_MAX / 128, HID / 128),   256, SM2 >>>();

    k_combine<<<T_TOK, 256>>>(out);
}